// round 2
// baseline (speedup 1.0000x reference)
#include <cuda_runtime.h>
#include <cuda_bf16.h>
#include <cstdint>

#define NN   8192            // nodes
#define EE   262144          // edges
#define D0   128             // input dim
#define HD   256             // hidden dim

typedef unsigned long long ull;

// ---------------- device scratch ----------------
__device__ float g_agg[NN * HD];
__device__ float g_h[NN * HD];
__device__ float g_dinv[NN];
__device__ int   g_cnt[NN];
__device__ int   g_off[NN + 1];
__device__ int   g_cur[NN];
__device__ int   g_col[EE];
__device__ float g_wval[EE];
__device__ float g_a[NN];
__device__ float g_b[NN];
__device__ float g_u[HD];
__device__ float g_v[HD];
__device__ float g_consts[2];
__device__ int   g_is64;

// ---------------- f32x2 packed helpers ----------------
__device__ __forceinline__ ull pack2(float v) {
    ull r; unsigned int b = __float_as_uint(v);
    asm("mov.b64 %0, {%1, %1};" : "=l"(r) : "r"(b));
    return r;
}
__device__ __forceinline__ void ffma2(ull& d, ull a, ull b) {
    asm("fma.rn.f32x2 %0, %1, %2, %0;" : "+l"(d) : "l"(a), "l"(b));
}
__device__ __forceinline__ float2 unpack2(ull v) {
    unsigned int lo, hi;
    asm("mov.b64 {%0, %1}, %2;" : "=r"(lo), "=r"(hi) : "l"(v));
    return make_float2(__uint_as_float(lo), __uint_as_float(hi));
}

// ---------------- edge index access ----------------
__device__ __forceinline__ int edge_at(const void* ei, int idx) {
    if (g_is64) return (int)((const long long*)ei)[idx];
    return ((const int*)ei)[idx];
}

// ---------------- prep: zero counts + dtype detect ----------------
__global__ void prep_kernel(const void* ei) {
    int i = blockIdx.x * blockDim.x + threadIdx.x;
    if (i < NN) g_cnt[i] = 0;
    if (i == 0) {
        const int* w = (const int*)ei;
        int is64 = 1;
        for (int t = 0; t < 32; t++)
            if (w[2 * t + 1] != 0) { is64 = 0; break; }
        g_is64 = is64;
    }
}

__global__ void count_kernel(const void* ei) {
    int e = blockIdx.x * blockDim.x + threadIdx.x;
    if (e >= EE) return;
    int d = edge_at(ei, EE + e);
    atomicAdd(&g_cnt[d], 1);
}

// one block, 1024 threads; 8 counts/thread; also computes dinv
__global__ void scan_kernel() {
    __shared__ int s[1024];
    int tid = threadIdx.x;
    int base = tid * 8;
    int c[8];
    int local = 0;
#pragma unroll
    for (int j = 0; j < 8; j++) { c[j] = g_cnt[base + j]; local += c[j]; }
    s[tid] = local;
    __syncthreads();
    for (int o = 1; o < 1024; o <<= 1) {
        int v = (tid >= o) ? s[tid - o] : 0;
        __syncthreads();
        s[tid] += v;
        __syncthreads();
    }
    int run = s[tid] - local;
#pragma unroll
    for (int j = 0; j < 8; j++) {
        g_off[base + j] = run;
        g_cur[base + j] = run;
        g_dinv[base + j] = rsqrtf((float)(c[j] + 1));  // +1 self loop
        run += c[j];
    }
    if (tid == 1023) g_off[NN] = run;
}

__global__ void fill_kernel(const void* ei) {
    int e = blockIdx.x * blockDim.x + threadIdx.x;
    if (e >= EE) return;
    int srow = edge_at(ei, e);
    int d    = edge_at(ei, EE + e);
    int pos = atomicAdd(&g_cur[d], 1);
    g_col[pos]  = srow;
    g_wval[pos] = g_dinv[srow];
}

// ---------------- aggregation with smem-staged edge chunks --------------
template <int H>
__global__ __launch_bounds__(256) void agg_kernel(const float* __restrict__ in_opt) {
    constexpr int TPR = H / 4;        // threads per row
    constexpr int RPB = 256 / TPR;    // rows per block
    __shared__ int   s_col[RPB][64];
    __shared__ float s_w[RPB][64];
    __shared__ int   s_max;
    const float* in = in_opt ? in_opt : g_h;
    int lane = threadIdx.x % TPR;
    int r    = threadIdx.x / TPR;
    int row  = blockIdx.x * RPB + r;
    if (threadIdx.x == 0) s_max = 0;
    __syncthreads();
    int e0 = g_off[row], e1 = g_off[row + 1];
    int deg = e1 - e0;
    if (lane == 0) atomicMax(&s_max, deg);
    const float4* in4 = (const float4*)in;
    float di = g_dinv[row];
    float4 sv = in4[(size_t)row * TPR + lane];
    float4 acc = make_float4(di * sv.x, di * sv.y, di * sv.z, di * sv.w);
    __syncthreads();
    int m = s_max;
    for (int c0 = 0; c0 < m; c0 += 64) {
        for (int j = lane; j < 64; j += TPR) {
            bool v = (c0 + j) < deg;
            int idx = e0 + c0 + j;
            s_col[r][j] = v ? g_col[idx] : 0;
            s_w[r][j]   = v ? g_wval[idx] : 0.0f;
        }
        __syncthreads();
        int cnt = deg - c0;
        cnt = cnt > 64 ? 64 : (cnt < 0 ? 0 : cnt);
#pragma unroll 4
        for (int j = 0; j < cnt; j++) {
            float w = s_w[r][j];
            float4 xv = in4[(size_t)s_col[r][j] * TPR + lane];
            acc.x = fmaf(w, xv.x, acc.x);
            acc.y = fmaf(w, xv.y, acc.y);
            acc.z = fmaf(w, xv.z, acc.z);
            acc.w = fmaf(w, xv.w, acc.w);
        }
        __syncthreads();
    }
    acc.x *= di; acc.y *= di; acc.z *= di; acc.w *= di;
    ((float4*)g_agg)[(size_t)row * TPR + lane] = acc;
}

// ---------------- fp32 GEMM with packed f32x2 FFMA ----------------------
// C[M,256] = relu(A[M,K] @ W[256,K]^T + b).  BM=64, BN=128, BK=8.
// 256 threads, 4x8 micro-tile, A staged as duplicated f32x2 in smem.
template <int K>
__global__ __launch_bounds__(256) void gemm_kernel(
    const float* __restrict__ W, const float* __restrict__ bias, int relu)
{
    __shared__ ull   As2[2][8][64];    // duplicated (a,a) pairs
    __shared__ float Bs[2][8][128];
    int bx = blockIdx.x;               // 0..1  col block (128 wide)
    int by = blockIdx.y;               // 0..127 row block (64 tall)
    int tid = threadIdx.x;
    int tx = tid & 15, ty = tid >> 4;
    int lr = tid >> 1;                 // 0..127
    int lk = (tid & 1) * 4;            // 0 / 4

    const float* Aptr = g_agg + (size_t)(by * 64 + lr) * K + lk;  // tid<128
    const float* Wptr = W + (size_t)(bx * 128 + lr) * K + lk;

    float4 av = make_float4(0.f, 0.f, 0.f, 0.f);
    float4 wv = *(const float4*)Wptr;
    if (tid < 128) av = *(const float4*)Aptr;
    if (tid < 128) {
        As2[0][lk + 0][lr] = pack2(av.x);
        As2[0][lk + 1][lr] = pack2(av.y);
        As2[0][lk + 2][lr] = pack2(av.z);
        As2[0][lk + 3][lr] = pack2(av.w);
    }
    Bs[0][lk + 0][lr] = wv.x; Bs[0][lk + 1][lr] = wv.y;
    Bs[0][lk + 2][lr] = wv.z; Bs[0][lk + 3][lr] = wv.w;
    __syncthreads();

    ull acc[4][4] = {};                // packed (0,0) == 0ull
    constexpr int NC = K / 8;
#pragma unroll 2
    for (int c = 0; c < NC; c++) {
        int buf = c & 1;
        float4 av2 = make_float4(0.f, 0.f, 0.f, 0.f), wv2;
        if (c + 1 < NC) {
            wv2 = *(const float4*)(Wptr + (c + 1) * 8);
            if (tid < 128) av2 = *(const float4*)(Aptr + (c + 1) * 8);
        }
#pragma unroll
        for (int k = 0; k < 8; k++) {
            const ull* Au = &As2[buf][k][0];
            const ull* Bu = (const ull*)&Bs[buf][k][0];
            ull a2[4], b2[4];
#pragma unroll
            for (int i = 0; i < 4; i++) a2[i] = Au[ty * 4 + i];
            b2[0] = Bu[tx * 2];      b2[1] = Bu[tx * 2 + 1];
            b2[2] = Bu[32 + tx * 2]; b2[3] = Bu[32 + tx * 2 + 1];
#pragma unroll
            for (int i = 0; i < 4; i++) {
                ffma2(acc[i][0], a2[i], b2[0]);
                ffma2(acc[i][1], a2[i], b2[1]);
                ffma2(acc[i][2], a2[i], b2[2]);
                ffma2(acc[i][3], a2[i], b2[3]);
            }
        }
        if (c + 1 < NC) {
            int nb = buf ^ 1;
            if (tid < 128) {
                As2[nb][lk + 0][lr] = pack2(av2.x);
                As2[nb][lk + 1][lr] = pack2(av2.y);
                As2[nb][lk + 2][lr] = pack2(av2.z);
                As2[nb][lk + 3][lr] = pack2(av2.w);
            }
            Bs[nb][lk + 0][lr] = wv2.x; Bs[nb][lk + 1][lr] = wv2.y;
            Bs[nb][lk + 2][lr] = wv2.z; Bs[nb][lk + 3][lr] = wv2.w;
            __syncthreads();
        }
    }

    // epilogue: bias + relu + store
    float4 bv0 = *(const float4*)&bias[bx * 128 + tx * 4];
    float4 bv1 = *(const float4*)&bias[bx * 128 + 64 + tx * 4];
#pragma unroll
    for (int i = 0; i < 4; i++) {
        int row = by * 64 + ty * 4 + i;
        float2 p0 = unpack2(acc[i][0]), p1 = unpack2(acc[i][1]);
        float2 p2 = unpack2(acc[i][2]), p3 = unpack2(acc[i][3]);
        float4 o0 = make_float4(p0.x + bv0.x, p0.y + bv0.y,
                                p1.x + bv0.z, p1.y + bv0.w);
        float4 o1 = make_float4(p2.x + bv1.x, p2.y + bv1.y,
                                p3.x + bv1.z, p3.y + bv1.w);
        if (relu) {
            o0.x = fmaxf(o0.x, 0.f); o0.y = fmaxf(o0.y, 0.f);
            o0.z = fmaxf(o0.z, 0.f); o0.w = fmaxf(o0.w, 0.f);
            o1.x = fmaxf(o1.x, 0.f); o1.y = fmaxf(o1.y, 0.f);
            o1.z = fmaxf(o1.z, 0.f); o1.w = fmaxf(o1.w, 0.f);
        }
        *(float4*)&g_h[(size_t)row * HD + bx * 128 + tx * 4] = o0;
        *(float4*)&g_h[(size_t)row * HD + bx * 128 + 64 + tx * 4] = o1;
    }
}

// ---------------- u = out_W^T wi, v = out_W^T wj, constants ----------------
__global__ void uv_kernel(const float* __restrict__ outW,
                          const float* __restrict__ outb,
                          const float* __restrict__ edgeW,
                          const float* __restrict__ edgeb) {
    int k = threadIdx.x;  // 256
    float su = 0.f, sv = 0.f;
    for (int j = 0; j < HD; j++) {
        float w = outW[j * HD + k];
        su += w * edgeW[j];
        sv += w * edgeW[HD + j];
    }
    g_u[k] = su;
    g_v[k] = sv;
    if (k == 0) {
        float ca = edgeb[0], cb = 0.f;
        for (int j = 0; j < HD; j++) {
            ca += outb[j] * edgeW[j];
            cb += outb[j] * edgeW[HD + j];
        }
        g_consts[0] = ca;
        g_consts[1] = cb;
    }
}

// ---------------- a[i] = h_i . u + ca ; b[i] = h_i . v + cb ----------------
__global__ void ab_kernel() {
    int warp = threadIdx.x >> 5, lane = threadIdx.x & 31;
    int node = blockIdx.x * 8 + warp;
    const float4* h4 = (const float4*)(g_h + (size_t)node * HD);
    const float4* u4 = (const float4*)g_u;
    const float4* v4 = (const float4*)g_v;
    float su = 0.f, sv = 0.f;
#pragma unroll
    for (int t = 0; t < 2; t++) {
        int idx = lane + t * 32;
        float4 hv = h4[idx];
        float4 uu = u4[idx];
        float4 vv = v4[idx];
        su += hv.x * uu.x + hv.y * uu.y + hv.z * uu.z + hv.w * uu.w;
        sv += hv.x * vv.x + hv.y * vv.y + hv.z * vv.z + hv.w * vv.w;
    }
#pragma unroll
    for (int o = 16; o > 0; o >>= 1) {
        su += __shfl_down_sync(0xffffffffu, su, o);
        sv += __shfl_down_sync(0xffffffffu, sv, o);
    }
    if (lane == 0) {
        g_a[node] = su + g_consts[0];
        g_b[node] = sv + g_consts[1];
    }
}

// ---------------- logits[i,j] = a[i] + b[j] ----------------
__global__ __launch_bounds__(256) void outer_kernel(float* __restrict__ out) {
    int i = blockIdx.x;
    float ai = g_a[i];
    float4* o = (float4*)(out + (size_t)i * NN);
    const float4* b4 = (const float4*)g_b;
#pragma unroll
    for (int t = 0; t < 8; t++) {
        int j = threadIdx.x + t * 256;
        float4 bv = __ldg(&b4[j]);
        float4 r = make_float4(ai + bv.x, ai + bv.y, ai + bv.z, ai + bv.w);
        __stcs(&o[j], r);
    }
}

// ---------------- launch ----------------------------------------------------
extern "C" void kernel_launch(void* const* d_in, const int* in_sizes, int n_in,
                              void* d_out, int out_size) {
    const float* x     = (const float*)d_in[0];
    const void*  ei    = d_in[1];
    const float* W0    = (const float*)d_in[2];
    const float* b0    = (const float*)d_in[3];
    const float* W1    = (const float*)d_in[4];
    const float* b1    = (const float*)d_in[5];
    const float* W2    = (const float*)d_in[6];
    const float* b2    = (const float*)d_in[7];
    const float* outW  = (const float*)d_in[8];
    const float* outb  = (const float*)d_in[9];
    const float* edgeW = (const float*)d_in[10];
    const float* edgeb = (const float*)d_in[11];
    float* out = (float*)d_out;

    dim3 ggrid(2, 128);

    prep_kernel<<<NN / 256, 256>>>(ei);        // 1
    count_kernel<<<EE / 256, 256>>>(ei);       // 2
    scan_kernel<<<1, 1024>>>();                // 3 (offsets + dinv)
    fill_kernel<<<EE / 256, 256>>>(ei);        // 4

    agg_kernel<D0><<<NN / 8, 256>>>(x);        // 5
    gemm_kernel<D0><<<ggrid, 256>>>(W0, b0, 1);// 6  <- ncu -s 5 captures this

    agg_kernel<HD><<<NN / 4, 256>>>(nullptr);  // 7
    gemm_kernel<HD><<<ggrid, 256>>>(W1, b1, 1);// 8

    agg_kernel<HD><<<NN / 4, 256>>>(nullptr);  // 9
    gemm_kernel<HD><<<ggrid, 256>>>(W2, b2, 1);// 10

    uv_kernel<<<1, HD>>>(outW, outb, edgeW, edgeb); // 11
    ab_kernel<<<NN / 8, 256>>>();              // 12
    outer_kernel<<<NN, 256>>>(out);            // 13
}

// round 3
// speedup vs baseline: 1.0321x; 1.0321x over previous
#include <cuda_runtime.h>
#include <cuda_bf16.h>
#include <cstdint>

#define NN   8192            // nodes
#define EE   262144          // edges
#define D0   128             // input dim
#define HD   256             // hidden dim

typedef unsigned long long ull;

// ---------------- device scratch (BSS: zero at load) ----------------
__device__ float g_agg[NN * HD];
__device__ float g_h[NN * HD];
__device__ float g_dinv[NN];
__device__ int   g_cnt[NN];      // self-zeroing: scan re-zeroes after read
__device__ int   g_off[NN + 1];
__device__ int   g_cur[NN];
__device__ ull   g_cw[EE];       // packed (src, weight)
__device__ float g_a[NN];
__device__ float g_b[NN];
__device__ float g_u[HD];
__device__ float g_v[HD];
__device__ float g_consts[2];
__device__ int   g_is64;

// ---------------- f32x2 packed helpers ----------------
__device__ __forceinline__ ull pack2(float v) {
    ull r; unsigned int b = __float_as_uint(v);
    asm("mov.b64 %0, {%1, %1};" : "=l"(r) : "r"(b));
    return r;
}
__device__ __forceinline__ void ffma2(ull& d, ull a, ull b) {
    asm("fma.rn.f32x2 %0, %1, %2, %0;" : "+l"(d) : "l"(a), "l"(b));
}
__device__ __forceinline__ float2 unpack2(ull v) {
    unsigned int lo, hi;
    asm("mov.b64 {%0, %1}, %2;" : "=r"(lo), "=r"(hi) : "l"(v));
    return make_float2(__uint_as_float(lo), __uint_as_float(hi));
}

// ---------------- edge helpers ----------------
__device__ __forceinline__ int edge_at(const void* ei, int idx, bool is64) {
    if (is64) return (int)((const long long*)ei)[idx];
    return ((const int*)ei)[idx];
}
// branchless int32-vs-int64 detect: OR of first 32 odd words (int64 hi words)
__device__ __forceinline__ int detect64(const void* ei) {
    const int* w = (const int*)ei;
    int acc = 0;
#pragma unroll
    for (int t = 0; t < 32; t++) acc |= w[2 * t + 1];
    return acc == 0;
}

// ---------------- CSR: count (8 edges/thread, g_cnt pre-zeroed) ----------
__global__ void count_kernel(const void* ei) {
    __shared__ int s64;
    if (threadIdx.x == 0) {
        s64 = detect64(ei);
        if (blockIdx.x == 0) g_is64 = s64;
    }
    __syncthreads();
    bool is64 = s64;
    int base = (blockIdx.x * blockDim.x + threadIdx.x) * 8;
    int d[8];
#pragma unroll
    for (int j = 0; j < 8; j++) d[j] = edge_at(ei, EE + base + j, is64);
#pragma unroll
    for (int j = 0; j < 8; j++) atomicAdd(&g_cnt[d[j]], 1);
}

// ---------------- scan: shfl-based, also dinv + zero g_cnt ----------------
__global__ void scan_kernel() {
    int tid = threadIdx.x, lane = tid & 31, warp = tid >> 5;
    int base = tid * 8;
    int c[8], local = 0;
#pragma unroll
    for (int j = 0; j < 8; j++) { c[j] = g_cnt[base + j]; local += c[j]; }
    int v = local;
#pragma unroll
    for (int o = 1; o < 32; o <<= 1) {
        int t = __shfl_up_sync(0xffffffffu, v, o);
        if (lane >= o) v += t;
    }
    __shared__ int ws[32];
    if (lane == 31) ws[warp] = v;
    __syncthreads();
    if (warp == 0) {
        int wv = ws[lane];
#pragma unroll
        for (int o = 1; o < 32; o <<= 1) {
            int t = __shfl_up_sync(0xffffffffu, wv, o);
            if (lane >= o) wv += t;
        }
        ws[lane] = wv;
    }
    __syncthreads();
    int run = v - local + (warp ? ws[warp - 1] : 0);
#pragma unroll
    for (int j = 0; j < 8; j++) {
        g_off[base + j] = run;
        g_cur[base + j] = run;
        g_dinv[base + j] = rsqrtf((float)(c[j] + 1));  // +1 self loop
        g_cnt[base + j] = 0;                           // re-arm for next replay
        run += c[j];
    }
    if (tid == 0) g_off[NN] = EE;
}

// ---------------- fill: 4 edges/thread, packed (col,weight) ----------------
__global__ void fill_kernel(const void* ei) {
    bool is64 = g_is64;
    int base = (blockIdx.x * blockDim.x + threadIdx.x) * 4;
    int s[4], d[4];
#pragma unroll
    for (int j = 0; j < 4; j++) {
        s[j] = edge_at(ei, base + j, is64);
        d[j] = edge_at(ei, EE + base + j, is64);
    }
    float w[4];
#pragma unroll
    for (int j = 0; j < 4; j++) w[j] = g_dinv[s[j]];
    int pos[4];
#pragma unroll
    for (int j = 0; j < 4; j++) pos[j] = atomicAdd(&g_cur[d[j]], 1);
#pragma unroll
    for (int j = 0; j < 4; j++)
        g_cw[pos[j]] = (ull)(unsigned)s[j] | ((ull)__float_as_uint(w[j]) << 32);
}

// ---------------- aggregation: independent warps, 4-way unrolled gather ----
template <int H>
__global__ __launch_bounds__(256) void agg_kernel(const float* __restrict__ in_opt) {
    constexpr int TPR = H / 4;        // threads per row
    constexpr int RPB = 256 / TPR;    // rows per block
    const float* in = in_opt ? in_opt : g_h;
    int lane = threadIdx.x % TPR;
    int row  = blockIdx.x * RPB + threadIdx.x / TPR;
    const float4* in4 = (const float4*)in;
    float di = g_dinv[row];
    float4 sv = in4[(size_t)row * TPR + lane];
    float4 acc = make_float4(di * sv.x, di * sv.y, di * sv.z, di * sv.w);
    int e = g_off[row], e1 = g_off[row + 1];
    for (; e + 4 <= e1; e += 4) {
        ull c0 = __ldg(&g_cw[e]);
        ull c1 = __ldg(&g_cw[e + 1]);
        ull c2 = __ldg(&g_cw[e + 2]);
        ull c3 = __ldg(&g_cw[e + 3]);
        int s0 = (int)(unsigned)c0, s1 = (int)(unsigned)c1;
        int s2 = (int)(unsigned)c2, s3 = (int)(unsigned)c3;
        float4 v0 = in4[(size_t)s0 * TPR + lane];
        float4 v1 = in4[(size_t)s1 * TPR + lane];
        float4 v2 = in4[(size_t)s2 * TPR + lane];
        float4 v3 = in4[(size_t)s3 * TPR + lane];
        float w0 = __uint_as_float((unsigned)(c0 >> 32));
        float w1 = __uint_as_float((unsigned)(c1 >> 32));
        float w2 = __uint_as_float((unsigned)(c2 >> 32));
        float w3 = __uint_as_float((unsigned)(c3 >> 32));
        acc.x = fmaf(w0, v0.x, acc.x); acc.y = fmaf(w0, v0.y, acc.y);
        acc.z = fmaf(w0, v0.z, acc.z); acc.w = fmaf(w0, v0.w, acc.w);
        acc.x = fmaf(w1, v1.x, acc.x); acc.y = fmaf(w1, v1.y, acc.y);
        acc.z = fmaf(w1, v1.z, acc.z); acc.w = fmaf(w1, v1.w, acc.w);
        acc.x = fmaf(w2, v2.x, acc.x); acc.y = fmaf(w2, v2.y, acc.y);
        acc.z = fmaf(w2, v2.z, acc.z); acc.w = fmaf(w2, v2.w, acc.w);
        acc.x = fmaf(w3, v3.x, acc.x); acc.y = fmaf(w3, v3.y, acc.y);
        acc.z = fmaf(w3, v3.z, acc.z); acc.w = fmaf(w3, v3.w, acc.w);
    }
    for (; e < e1; e++) {
        ull c0 = __ldg(&g_cw[e]);
        int s0 = (int)(unsigned)c0;
        float w0 = __uint_as_float((unsigned)(c0 >> 32));
        float4 v0 = in4[(size_t)s0 * TPR + lane];
        acc.x = fmaf(w0, v0.x, acc.x); acc.y = fmaf(w0, v0.y, acc.y);
        acc.z = fmaf(w0, v0.z, acc.z); acc.w = fmaf(w0, v0.w, acc.w);
    }
    acc.x *= di; acc.y *= di; acc.z *= di; acc.w *= di;
    ((float4*)g_agg)[(size_t)row * TPR + lane] = acc;
}

// ---------------- fp32 GEMM with packed f32x2 FFMA (unchanged) -------------
template <int K>
__global__ __launch_bounds__(256) void gemm_kernel(
    const float* __restrict__ W, const float* __restrict__ bias, int relu)
{
    __shared__ ull   As2[2][8][64];    // duplicated (a,a) pairs
    __shared__ float Bs[2][8][128];
    int bx = blockIdx.x;
    int by = blockIdx.y;
    int tid = threadIdx.x;
    int tx = tid & 15, ty = tid >> 4;
    int lr = tid >> 1;
    int lk = (tid & 1) * 4;

    const float* Aptr = g_agg + (size_t)(by * 64 + lr) * K + lk;
    const float* Wptr = W + (size_t)(bx * 128 + lr) * K + lk;

    float4 av = make_float4(0.f, 0.f, 0.f, 0.f);
    float4 wv = *(const float4*)Wptr;
    if (tid < 128) av = *(const float4*)Aptr;
    if (tid < 128) {
        As2[0][lk + 0][lr] = pack2(av.x);
        As2[0][lk + 1][lr] = pack2(av.y);
        As2[0][lk + 2][lr] = pack2(av.z);
        As2[0][lk + 3][lr] = pack2(av.w);
    }
    Bs[0][lk + 0][lr] = wv.x; Bs[0][lk + 1][lr] = wv.y;
    Bs[0][lk + 2][lr] = wv.z; Bs[0][lk + 3][lr] = wv.w;
    __syncthreads();

    ull acc[4][4] = {};
    constexpr int NC = K / 8;
#pragma unroll 2
    for (int c = 0; c < NC; c++) {
        int buf = c & 1;
        float4 av2 = make_float4(0.f, 0.f, 0.f, 0.f), wv2;
        if (c + 1 < NC) {
            wv2 = *(const float4*)(Wptr + (c + 1) * 8);
            if (tid < 128) av2 = *(const float4*)(Aptr + (c + 1) * 8);
        }
#pragma unroll
        for (int k = 0; k < 8; k++) {
            const ull* Au = &As2[buf][k][0];
            const ull* Bu = (const ull*)&Bs[buf][k][0];
            ull a2[4], b2[4];
#pragma unroll
            for (int i = 0; i < 4; i++) a2[i] = Au[ty * 4 + i];
            b2[0] = Bu[tx * 2];      b2[1] = Bu[tx * 2 + 1];
            b2[2] = Bu[32 + tx * 2]; b2[3] = Bu[32 + tx * 2 + 1];
#pragma unroll
            for (int i = 0; i < 4; i++) {
                ffma2(acc[i][0], a2[i], b2[0]);
                ffma2(acc[i][1], a2[i], b2[1]);
                ffma2(acc[i][2], a2[i], b2[2]);
                ffma2(acc[i][3], a2[i], b2[3]);
            }
        }
        if (c + 1 < NC) {
            int nb = buf ^ 1;
            if (tid < 128) {
                As2[nb][lk + 0][lr] = pack2(av2.x);
                As2[nb][lk + 1][lr] = pack2(av2.y);
                As2[nb][lk + 2][lr] = pack2(av2.z);
                As2[nb][lk + 3][lr] = pack2(av2.w);
            }
            Bs[nb][lk + 0][lr] = wv2.x; Bs[nb][lk + 1][lr] = wv2.y;
            Bs[nb][lk + 2][lr] = wv2.z; Bs[nb][lk + 3][lr] = wv2.w;
            __syncthreads();
        }
    }

    float4 bv0 = *(const float4*)&bias[bx * 128 + tx * 4];
    float4 bv1 = *(const float4*)&bias[bx * 128 + 64 + tx * 4];
#pragma unroll
    for (int i = 0; i < 4; i++) {
        int row = by * 64 + ty * 4 + i;
        float2 p0 = unpack2(acc[i][0]), p1 = unpack2(acc[i][1]);
        float2 p2 = unpack2(acc[i][2]), p3 = unpack2(acc[i][3]);
        float4 o0 = make_float4(p0.x + bv0.x, p0.y + bv0.y,
                                p1.x + bv0.z, p1.y + bv0.w);
        float4 o1 = make_float4(p2.x + bv1.x, p2.y + bv1.y,
                                p3.x + bv1.z, p3.y + bv1.w);
        if (relu) {
            o0.x = fmaxf(o0.x, 0.f); o0.y = fmaxf(o0.y, 0.f);
            o0.z = fmaxf(o0.z, 0.f); o0.w = fmaxf(o0.w, 0.f);
            o1.x = fmaxf(o1.x, 0.f); o1.y = fmaxf(o1.y, 0.f);
            o1.z = fmaxf(o1.z, 0.f); o1.w = fmaxf(o1.w, 0.f);
        }
        *(float4*)&g_h[(size_t)row * HD + bx * 128 + tx * 4] = o0;
        *(float4*)&g_h[(size_t)row * HD + bx * 128 + 64 + tx * 4] = o1;
    }
}

// ---------------- u = out_W^T wi, v = out_W^T wj, constants ----------------
__global__ void uv_kernel(const float* __restrict__ outW,
                          const float* __restrict__ outb,
                          const float* __restrict__ edgeW,
                          const float* __restrict__ edgeb) {
    int k = threadIdx.x;  // 256
    float su = 0.f, sv = 0.f;
    for (int j = 0; j < HD; j++) {
        float w = outW[j * HD + k];
        su += w * edgeW[j];
        sv += w * edgeW[HD + j];
    }
    g_u[k] = su;
    g_v[k] = sv;
    if (k == 0) {
        float ca = edgeb[0], cb = 0.f;
        for (int j = 0; j < HD; j++) {
            ca += outb[j] * edgeW[j];
            cb += outb[j] * edgeW[HD + j];
        }
        g_consts[0] = ca;
        g_consts[1] = cb;
    }
}

// ---------------- a[i], b[i] dot products ----------------
__global__ void ab_kernel() {
    int warp = threadIdx.x >> 5, lane = threadIdx.x & 31;
    int node = blockIdx.x * 8 + warp;
    const float4* h4 = (const float4*)(g_h + (size_t)node * HD);
    const float4* u4 = (const float4*)g_u;
    const float4* v4 = (const float4*)g_v;
    float su = 0.f, sv = 0.f;
#pragma unroll
    for (int t = 0; t < 2; t++) {
        int idx = lane + t * 32;
        float4 hv = h4[idx];
        float4 uu = u4[idx];
        float4 vv = v4[idx];
        su += hv.x * uu.x + hv.y * uu.y + hv.z * uu.z + hv.w * uu.w;
        sv += hv.x * vv.x + hv.y * vv.y + hv.z * vv.z + hv.w * vv.w;
    }
#pragma unroll
    for (int o = 16; o > 0; o >>= 1) {
        su += __shfl_down_sync(0xffffffffu, su, o);
        sv += __shfl_down_sync(0xffffffffu, sv, o);
    }
    if (lane == 0) {
        g_a[node] = su + g_consts[0];
        g_b[node] = sv + g_consts[1];
    }
}

// ---------------- logits[i,j] = a[i] + b[j] ----------------
__global__ __launch_bounds__(256) void outer_kernel(float* __restrict__ out) {
    int i = blockIdx.x;
    float ai = g_a[i];
    float4* o = (float4*)(out + (size_t)i * NN);
    const float4* b4 = (const float4*)g_b;
#pragma unroll
    for (int t = 0; t < 8; t++) {
        int j = threadIdx.x + t * 256;
        float4 bv = __ldg(&b4[j]);
        float4 r = make_float4(ai + bv.x, ai + bv.y, ai + bv.z, ai + bv.w);
        __stcs(&o[j], r);
    }
}

// ---------------- launch ----------------------------------------------------
extern "C" void kernel_launch(void* const* d_in, const int* in_sizes, int n_in,
                              void* d_out, int out_size) {
    const float* x     = (const float*)d_in[0];
    const void*  ei    = d_in[1];
    const float* W0    = (const float*)d_in[2];
    const float* b0    = (const float*)d_in[3];
    const float* W1    = (const float*)d_in[4];
    const float* b1    = (const float*)d_in[5];
    const float* W2    = (const float*)d_in[6];
    const float* b2    = (const float*)d_in[7];
    const float* outW  = (const float*)d_in[8];
    const float* outb  = (const float*)d_in[9];
    const float* edgeW = (const float*)d_in[10];
    const float* edgeb = (const float*)d_in[11];
    float* out = (float*)d_out;

    dim3 ggrid(2, 128);

    count_kernel<<<EE / (256 * 8), 256>>>(ei);     // 1
    scan_kernel<<<1, 1024>>>();                    // 2 (off+cur+dinv, rearm cnt)
    fill_kernel<<<EE / (256 * 4), 256>>>(ei);      // 3

    agg_kernel<D0><<<NN / 8, 256>>>(x);            // 4  <- ncu captures this
    gemm_kernel<D0><<<ggrid, 256>>>(W0, b0, 1);    // 5

    agg_kernel<HD><<<NN / 4, 256>>>(nullptr);      // 6
    gemm_kernel<HD><<<ggrid, 256>>>(W1, b1, 1);    // 7

    agg_kernel<HD><<<NN / 4, 256>>>(nullptr);      // 8
    gemm_kernel<HD><<<ggrid, 256>>>(W2, b2, 1);    // 9

    uv_kernel<<<1, HD>>>(outW, outb, edgeW, edgeb);// 10
    ab_kernel<<<NN / 8, 256>>>();                  // 11
    outer_kernel<<<NN, 256>>>(out);                // 12
}